// round 7
// baseline (speedup 1.0000x reference)
#include <cuda_runtime.h>
#include <cuda_bf16.h>

// NeighborSearch_batch via 33x33 uniform grid, slotted cells (no scan),
// one-warp-per-query search, rank-selection emit (deterministic, sorted).
// B=8, n=9225 data pts, m=4096 queries, d=2, radius=0.03
// Output (float32): neighbors_index [B, m, 64] then row_splits [B, m+1].

#define BATCH  8
#define NPTS   9225
#define NQ     4096
#define MAXN   64
#define GRID   33
#define NCELLS (GRID * GRID)
#define CAP    64     // per-query accept capacity (reference: observed max ~50)
#define SLOTC  48     // per-cell point capacity; Poisson(8.47) overflow ~1e-11

__device__ int    g_ccnt  [BATCH * NCELLS];
__device__ float4 g_slots [BATCH * NCELLS * SLOTC];  // (x, y, dn, idx bits)
__device__ int    g_counts[BATCH * NQ];

__device__ __forceinline__ int cell_of(float x, float y) {
    int cx = (int)(x * (float)GRID); if (cx > GRID - 1) cx = GRID - 1; if (cx < 0) cx = 0;
    int cy = (int)(y * (float)GRID); if (cy > GRID - 1) cy = GRID - 1; if (cy < 0) cy = 0;
    return cy * GRID + cx;
}

__global__ void zero_kernel() {
    int i = blockIdx.x * blockDim.x + threadIdx.x;
    if (i < BATCH * NCELLS) g_ccnt[i] = 0;
}

// one pass: point -> cell slot (global cursor atomics, spread across LTS)
__global__ void scatter_kernel(const float* __restrict__ data) {
    int i = blockIdx.x * blockDim.x + threadIdx.x;
    if (i >= BATCH * NPTS) return;
    int b = i / NPTS;
    int j = i - b * NPTS;
    const float2 pf = ((const float2*)data)[i];
    const float px = pf.x, py = pf.y;
    // dn = RN(RN(x*x) + RN(y*y))  (matches jnp.sum(data*data))
    const float dn = __fadd_rn(__fmul_rn(px, px), __fmul_rn(py, py));
    const int c = b * NCELLS + cell_of(px, py);
    const int pos = atomicAdd(&g_ccnt[c], 1);
    g_slots[(size_t)c * SLOTC + pos] = make_float4(px, py, dn, __int_as_float(j));
}

// one warp per query: 32 lanes sweep 3x3 cell slot-lists, ballot-compact,
// rank-selection emit (order-independent => deterministic sorted output).
#define WPB 8
__global__ void __launch_bounds__(WPB * 32)
query_kernel(const float* __restrict__ queries,
             const float* __restrict__ radius,
             float* __restrict__ nbr_idx)
{
    __shared__ unsigned short cand[WPB][CAP];

    const int lane = threadIdx.x & 31;
    const int wid  = threadIdx.x >> 5;
    const int b = blockIdx.y;
    const int q = blockIdx.x * WPB + wid;

    const float2 qf = ((const float2*)queries)[(size_t)b * NQ + q];
    const float q0 = qf.x, q1 = qf.y;
    // qn = RN(RN(q0*q0) + RN(q1*q1))
    const float qn = __fadd_rn(__fmul_rn(q0, q0), __fmul_rn(q1, q1));

    const float r  = radius[0];
    const float r2 = __fmul_rn(r, r);
    int reach = (int)ceilf(r * (float)GRID);
    if (reach < 1) reach = 1;

    int cx = (int)(q0 * (float)GRID); if (cx > GRID - 1) cx = GRID - 1; if (cx < 0) cx = 0;
    int cy = (int)(q1 * (float)GRID); if (cy > GRID - 1) cy = GRID - 1; if (cy < 0) cy = 0;
    const int x0 = max(0, cx - reach), x1 = min(GRID - 1, cx + reach);
    const int y0 = max(0, cy - reach), y1 = min(GRID - 1, cy + reach);

    int cnt = 0;

    for (int gy = y0; gy <= y1; ++gy) {
        for (int gx = x0; gx <= x1; ++gx) {
            const int c = b * NCELLS + gy * GRID + gx;
            const int nc = g_ccnt[c];
            const float4* cp = g_slots + (size_t)c * SLOTC;
            for (int i0 = 0; i0 < nc; i0 += 32) {
                const int i = i0 + lane;
                bool acc = false;
                int idx = 0;
                if (i < nc) {
                    const float4 p = cp[i];
                    // cross = RN(RN(q0*px) + RN(q1*py)); 2*cross exact (self-add)
                    const float cr = __fadd_rn(__fmul_rn(q0, p.x), __fmul_rn(q1, p.y));
                    // v = RN(RN(qn + dn) - 2*cross)
                    const float v  = __fsub_rn(__fadd_rn(qn, p.z), __fadd_rn(cr, cr));
                    acc = (v <= r2);
                    idx = __float_as_int(p.w);
                }
                const unsigned bal = __ballot_sync(0xFFFFFFFFu, acc);
                if (acc) {
                    const int s = cnt + __popc(bal & ((1u << lane) - 1u));
                    if (s < CAP) cand[wid][s] = (unsigned short)idx;
                }
                cnt += __popc(bal);
            }
        }
    }

    __syncwarp();

    float* out = nbr_idx + ((size_t)(b * NQ + q)) * MAXN;
    const int k = cnt < CAP ? cnt : CAP;

    // -1 fill, warp-parallel (slots k..63)
    for (int s = k + lane; s < MAXN; s += 32) out[s] = -1.0f;

    // rank-selection emit: rank_i = #{j : v_j < v_i} is a permutation of
    // 0..k-1 (indices distinct) -> sorted output, scatter-order independent.
    // cand[wid][j] is the same address across lanes -> LDS broadcast.
    for (int i = lane; i < k; i += 32) {
        const int v = cand[wid][i];
        int rank = 0;
        for (int j = 0; j < k; ++j)
            rank += (cand[wid][j] < v) ? 1 : 0;
        out[rank] = (float)v;   // rank <= k-1 < MAXN
    }

    if (lane == 0) g_counts[b * NQ + q] = cnt;
}

// per-batch exclusive prefix sum over 4096 counts -> row_splits[b][0..4096]
__global__ void __launch_bounds__(1024)
row_splits_kernel(float* __restrict__ row_splits)
{
    __shared__ int warp_sums[32];
    const int b = blockIdx.x;
    const int t = threadIdx.x;
    const int lane = t & 31, wid = t >> 5;

    const int* c = g_counts + b * NQ;
    const int base = t * 4;
    const int c0 = c[base + 0], c1 = c[base + 1], c2 = c[base + 2], c3 = c[base + 3];
    const int s0 = c0, s1 = s0 + c1, s2 = s1 + c2, s3 = s2 + c3;
    const int total = s3;

    int x = total;
    #pragma unroll
    for (int o = 1; o < 32; o <<= 1) {
        int y = __shfl_up_sync(0xFFFFFFFFu, x, o);
        if (lane >= o) x += y;
    }
    if (lane == 31) warp_sums[wid] = x;
    __syncthreads();
    if (wid == 0) {
        int w = warp_sums[lane];
        #pragma unroll
        for (int o = 1; o < 32; o <<= 1) {
            int y = __shfl_up_sync(0xFFFFFFFFu, w, o);
            if (lane >= o) w += y;
        }
        warp_sums[lane] = w;
    }
    __syncthreads();

    const int excl = (x - total) + (wid > 0 ? warp_sums[wid - 1] : 0);
    float* rs = row_splits + b * (NQ + 1);
    if (t == 0) rs[0] = 0.0f;
    rs[base + 1] = (float)(excl + s0);
    rs[base + 2] = (float)(excl + s1);
    rs[base + 3] = (float)(excl + s2);
    rs[base + 4] = (float)(excl + s3);
}

extern "C" void kernel_launch(void* const* d_in, const int* in_sizes, int n_in,
                              void* d_out, int out_size)
{
    const float* data    = (const float*)d_in[0];   // [8, 9225, 2]
    const float* queries = (const float*)d_in[1];   // [8, 4096, 2]
    const float* radius  = (const float*)d_in[2];   // scalar

    float* nbr_idx    = (float*)d_out;                          // [8, 4096, 64]
    float* row_splits = nbr_idx + (size_t)BATCH * NQ * MAXN;    // [8, 4097]

    zero_kernel   <<<(BATCH * NCELLS + 255) / 256, 256>>>();
    scatter_kernel<<<(BATCH * NPTS + 255) / 256, 256>>>(data);

    dim3 qgrid(NQ / WPB, BATCH);
    query_kernel  <<<qgrid, WPB * 32>>>(queries, radius, nbr_idx);
    row_splits_kernel<<<BATCH, 1024>>>(row_splits);
}

// round 8
// speedup vs baseline: 1.0239x; 1.0239x over previous
#include <cuda_runtime.h>
#include <cuda_bf16.h>

// NeighborSearch_batch via 33x33 uniform grid, slotted cells (no scan),
// 4-lanes-per-query search with unrolled 3x3 window, rank-selection emit.
// B=8, n=9225 data pts, m=4096 queries, d=2, radius=0.03
// Output (float32): neighbors_index [B, m, 64] then row_splits [B, m+1].

#define BATCH  8
#define NPTS   9225
#define NQ     4096
#define MAXN   64
#define GRID   33
#define NCELLS (GRID * GRID)
#define CAP    64     // per-query accept capacity (reference: observed max ~50)
#define SLOTC  48     // per-cell capacity; Poisson(8.47) overflow ~1e-11

#define LPQ    4                  // lanes per query
#define QPB    32                 // queries per CTA
#define QTPB   (LPQ * QPB)        // 128 threads

// NOTE: __device__ globals are zero-initialized at module load; g_ccnt is
// re-zeroed at the END of every run (in row_splits_kernel), so each graph
// replay starts from the same state without a zeroing launch.
__device__ int    g_ccnt  [BATCH * NCELLS];
__device__ float4 g_slots [BATCH * NCELLS * SLOTC];  // (x, y, dn, idx bits)
__device__ int    g_counts[BATCH * NQ];

__device__ __forceinline__ int clampi(int v, int lo, int hi) {
    return v < lo ? lo : (v > hi ? hi : v);
}

// one pass: point -> cell slot (global cursor atomics, spread across LTS)
__global__ void scatter_kernel(const float* __restrict__ data) {
    int i = blockIdx.x * blockDim.x + threadIdx.x;
    if (i >= BATCH * NPTS) return;
    int b = i / NPTS;
    int j = i - b * NPTS;
    const float2 pf = ((const float2*)data)[i];
    const float px = pf.x, py = pf.y;
    // dn = RN(RN(x*x) + RN(y*y))  (matches jnp.sum(data*data))
    const float dn = __fadd_rn(__fmul_rn(px, px), __fmul_rn(py, py));
    const int cx = clampi((int)(px * (float)GRID), 0, GRID - 1);
    const int cy = clampi((int)(py * (float)GRID), 0, GRID - 1);
    const int c = b * NCELLS + cy * GRID + cx;
    const int pos = atomicAdd(&g_ccnt[c], 1);
    if (pos < SLOTC)
        g_slots[(size_t)c * SLOTC + pos] = make_float4(px, py, dn, __int_as_float(j));
}

// 4 lanes per query; 3x3 window unrolled so all 9 cell headers load with
// MLP=9; ballot-compact accepts into smem; rank-selection emit
// (order-independent of atomic scatter order => deterministic).
__global__ void __launch_bounds__(QTPB)
query_kernel(const float* __restrict__ queries,
             const float* __restrict__ radius,
             float* __restrict__ nbr_idx)
{
    __shared__ int cand[CAP][QPB + 1];   // stride 33: conflict-free

    const int tid   = threadIdx.x;
    const int sub   = tid & (LPQ - 1);        // 0..3 within group
    const int qslot = tid >> 2;               // 0..31 query slot in CTA
    const int shift = (tid & 31) & ~(LPQ - 1);
    const unsigned gmask = 0xFu << shift;

    const int b = blockIdx.y;
    const int q = blockIdx.x * QPB + qslot;

    const float2 qf = ((const float2*)queries)[(size_t)b * NQ + q];
    const float q0 = qf.x, q1 = qf.y;
    // qn = RN(RN(q0*q0) + RN(q1*q1))
    const float qn = __fadd_rn(__fmul_rn(q0, q0), __fmul_rn(q1, q1));

    const float r  = radius[0];
    const float r2 = __fmul_rn(r, r);
    int reach = (int)ceilf(r * (float)GRID);
    if (reach < 1) reach = 1;

    const int cx = clampi((int)(q0 * (float)GRID), 0, GRID - 1);
    const int cy = clampi((int)(q1 * (float)GRID), 0, GRID - 1);

    int cnt = 0;

    if (reach == 1) {
        // fast path: fixed 3x3, predicated borders; headers load up-front
        int cell9[9], nc9[9];
        #pragma unroll
        for (int dy = -1; dy <= 1; ++dy) {
            #pragma unroll
            for (int dx = -1; dx <= 1; ++dx) {
                const int gx = cx + dx, gy = cy + dy;
                const bool ok = (gx >= 0) & (gx < GRID) & (gy >= 0) & (gy < GRID);
                const int c = b * NCELLS + gy * GRID + gx;
                const int e = 3 * (dy + 1) + (dx + 1);
                cell9[e] = c;
                nc9[e] = ok ? g_ccnt[c] : 0;   // 9 independent LDGs
            }
        }
        #pragma unroll
        for (int e = 0; e < 9; ++e) {
            const int nc = min(nc9[e], SLOTC);
            const float4* cp = g_slots + (size_t)cell9[e] * SLOTC;
            for (int ib = 0; ib < nc; ib += LPQ) {
                const int i = ib + sub;
                bool acc = false;
                int idx = 0;
                if (i < nc) {
                    const float4 p = cp[i];
                    // cross = RN(RN(q0*px)+RN(q1*py)); 2*cross exact (self-add)
                    const float cr = __fadd_rn(__fmul_rn(q0, p.x), __fmul_rn(q1, p.y));
                    // v = RN(RN(qn + dn) - 2*cross)
                    const float v  = __fsub_rn(__fadd_rn(qn, p.z), __fadd_rn(cr, cr));
                    acc = (v <= r2);
                    idx = __float_as_int(p.w);
                }
                const unsigned bal = __ballot_sync(gmask, acc);
                const unsigned nib = (bal >> shift) & 0xFu;
                if (acc) {
                    const int s = cnt + __popc(nib & ((1u << sub) - 1u));
                    if (s < CAP) cand[s][qslot] = idx;
                }
                cnt += __popc(nib);
            }
        }
    } else {
        // generic path (not taken for r=0.03, kept for correctness)
        const int x0 = max(0, cx - reach), x1 = min(GRID - 1, cx + reach);
        const int y0 = max(0, cy - reach), y1 = min(GRID - 1, cy + reach);
        for (int gy = y0; gy <= y1; ++gy) {
            for (int gx = x0; gx <= x1; ++gx) {
                const int c = b * NCELLS + gy * GRID + gx;
                const int nc = min(g_ccnt[c], SLOTC);
                const float4* cp = g_slots + (size_t)c * SLOTC;
                for (int ib = 0; ib < nc; ib += LPQ) {
                    const int i = ib + sub;
                    bool acc = false;
                    int idx = 0;
                    if (i < nc) {
                        const float4 p = cp[i];
                        const float cr = __fadd_rn(__fmul_rn(q0, p.x), __fmul_rn(q1, p.y));
                        const float v  = __fsub_rn(__fadd_rn(qn, p.z), __fadd_rn(cr, cr));
                        acc = (v <= r2);
                        idx = __float_as_int(p.w);
                    }
                    const unsigned bal = __ballot_sync(gmask, acc);
                    const unsigned nib = (bal >> shift) & 0xFu;
                    if (acc) {
                        const int s = cnt + __popc(nib & ((1u << sub) - 1u));
                        if (s < CAP) cand[s][qslot] = idx;
                    }
                    cnt += __popc(nib);
                }
            }
        }
    }

    float* out = nbr_idx + ((size_t)(b * NQ + q)) * MAXN;
    const int k = cnt < CAP ? cnt : CAP;

    // -1 fill (slots k..63), split across the 4 lanes
    for (int s = k + sub; s < MAXN; s += LPQ) out[s] = -1.0f;

    // rank-selection emit: rank_i = #{j : v_j < v_i} is a permutation of
    // 0..k-1 (indices distinct) -> sorted output, scatter-order independent.
    for (int i = sub; i < k; i += LPQ) {
        const int v = cand[i][qslot];
        int rank = 0;
        #pragma unroll 4
        for (int j = 0; j < k; ++j)
            rank += (cand[j][qslot] < v) ? 1 : 0;
        out[rank] = (float)v;   // rank <= k-1 < MAXN <= CAP
    }

    if (sub == 0) g_counts[b * NQ + q] = cnt;
}

// per-batch exclusive prefix sum over 4096 counts -> row_splits[b][0..4096];
// also re-zeroes g_ccnt for the next graph replay.
__global__ void __launch_bounds__(1024)
row_splits_kernel(float* __restrict__ row_splits)
{
    __shared__ int warp_sums[32];
    const int b = blockIdx.x;
    const int t = threadIdx.x;
    const int lane = t & 31, wid = t >> 5;

    const int* c = g_counts + b * NQ;
    const int base = t * 4;
    const int c0 = c[base + 0], c1 = c[base + 1], c2 = c[base + 2], c3 = c[base + 3];
    const int s0 = c0, s1 = s0 + c1, s2 = s1 + c2, s3 = s2 + c3;
    const int total = s3;

    // reset cell cursors for the next run (8 blocks cover 8712 ints)
    {
        const int i = b * 1024 + t;
        if (i < BATCH * NCELLS) g_ccnt[i] = 0;
        const int i2 = i + BATCH * 1024;
        if (i2 < BATCH * NCELLS) g_ccnt[i2] = 0;
    }

    int x = total;
    #pragma unroll
    for (int o = 1; o < 32; o <<= 1) {
        int y = __shfl_up_sync(0xFFFFFFFFu, x, o);
        if (lane >= o) x += y;
    }
    if (lane == 31) warp_sums[wid] = x;
    __syncthreads();
    if (wid == 0) {
        int w = warp_sums[lane];
        #pragma unroll
        for (int o = 1; o < 32; o <<= 1) {
            int y = __shfl_up_sync(0xFFFFFFFFu, w, o);
            if (lane >= o) w += y;
        }
        warp_sums[lane] = w;
    }
    __syncthreads();

    const int excl = (x - total) + (wid > 0 ? warp_sums[wid - 1] : 0);
    float* rs = row_splits + b * (NQ + 1);
    if (t == 0) rs[0] = 0.0f;
    rs[base + 1] = (float)(excl + s0);
    rs[base + 2] = (float)(excl + s1);
    rs[base + 3] = (float)(excl + s2);
    rs[base + 4] = (float)(excl + s3);
}

extern "C" void kernel_launch(void* const* d_in, const int* in_sizes, int n_in,
                              void* d_out, int out_size)
{
    const float* data    = (const float*)d_in[0];   // [8, 9225, 2]
    const float* queries = (const float*)d_in[1];   // [8, 4096, 2]
    const float* radius  = (const float*)d_in[2];   // scalar

    float* nbr_idx    = (float*)d_out;                          // [8, 4096, 64]
    float* row_splits = nbr_idx + (size_t)BATCH * NQ * MAXN;    // [8, 4097]

    scatter_kernel<<<(BATCH * NPTS + 255) / 256, 256>>>(data);

    dim3 qgrid(NQ / QPB, BATCH);
    query_kernel<<<qgrid, QTPB>>>(queries, radius, nbr_idx);
    row_splits_kernel<<<BATCH, 1024>>>(row_splits);
}